// round 1
// baseline (speedup 1.0000x reference)
#include <cuda_runtime.h>
#include <math.h>

// ---------------- problem constants ----------------
#define NN   50000
#define PP   3
#define EE   800000
#define FEATD 1000
#define HH   256
#define PHH  512
#define BN_EPS 1e-5f

// ---------------- device scratch (no allocations allowed) ----------------
__device__ float g_h [(size_t)NN * HH];   // elu(feats @ W_trans^T + b)
__device__ float g_ft[(size_t)NN * HH];   // per-view seq_fts (reused)
__device__ float g_z0[(size_t)NN * HH];   // gcn view0 (student)
__device__ float g_z1[(size_t)NN * HH];   // gcn view1 (teacher 1)
__device__ float g_z2[(size_t)NN * HH];   // gcn view2 (teacher 2)
__device__ float g_x [(size_t)NN * PHH];  // predictor hidden
__device__ float g_vp[(size_t)NN * HH];   // v_pred
__device__ float g_stats[2 * PHH];        // col sums / sumsq for BN
__device__ float g_beta_raw[3];
__device__ float g_beta[3];
__device__ float g_loss_acc;

// ---------------- generic fp32 GEMM: C[M,Nc] = act(A[M,K] @ W[Nc,K]^T + bias) ----
// EPI: 0 = store raw, 1 = bias + ELU, 2 = bias only
#define BM 64
#define BN 64
#define BKK 16

template<int EPI>
__global__ __launch_bounds__(256)
void gemm_tn_kernel(const float* __restrict__ A, const float* __restrict__ W,
                    const float* __restrict__ bias, float* __restrict__ C,
                    int M, int Nc, int K)
{
    __shared__ float As[BKK][BM];
    __shared__ float Ws[BKK][BN];

    const int tid  = threadIdx.x;           // 256 threads
    const int bm   = blockIdx.y * BM;
    const int bn   = blockIdx.x * BN;
    const int tx   = tid & 15;
    const int ty   = tid >> 4;
    const int lrow = tid >> 2;               // 0..63
    const int lq   = (tid & 3) * 4;          // 0,4,8,12

    float acc[4][4] = {};

    for (int k0 = 0; k0 < K; k0 += BKK) {
        float4 av = make_float4(0.f, 0.f, 0.f, 0.f);
        int gm = bm + lrow;
        if (gm < M && (k0 + lq) < K)
            av = *(const float4*)(A + (size_t)gm * K + k0 + lq);
        As[lq + 0][lrow] = av.x; As[lq + 1][lrow] = av.y;
        As[lq + 2][lrow] = av.z; As[lq + 3][lrow] = av.w;

        float4 wv = make_float4(0.f, 0.f, 0.f, 0.f);
        int gn = bn + lrow;
        if (gn < Nc && (k0 + lq) < K)
            wv = *(const float4*)(W + (size_t)gn * K + k0 + lq);
        Ws[lq + 0][lrow] = wv.x; Ws[lq + 1][lrow] = wv.y;
        Ws[lq + 2][lrow] = wv.z; Ws[lq + 3][lrow] = wv.w;

        __syncthreads();
#pragma unroll
        for (int k = 0; k < BKK; ++k) {
            float4 a4 = *(const float4*)(&As[k][ty << 2]);
            float4 b4 = *(const float4*)(&Ws[k][tx << 2]);
            float a[4] = {a4.x, a4.y, a4.z, a4.w};
            float b[4] = {b4.x, b4.y, b4.z, b4.w};
#pragma unroll
            for (int i = 0; i < 4; ++i)
#pragma unroll
                for (int j = 0; j < 4; ++j)
                    acc[i][j] += a[i] * b[j];
        }
        __syncthreads();
    }

    const int gm0 = bm + (ty << 2);
    const int gn0 = bn + (tx << 2);
    float4 bv = make_float4(0.f, 0.f, 0.f, 0.f);
    if (EPI >= 1) bv = *(const float4*)(bias + gn0);

#pragma unroll
    for (int i = 0; i < 4; ++i) {
        int gm = gm0 + i;
        if (gm >= M) break;
        float4 c;
        c.x = acc[i][0]; c.y = acc[i][1]; c.z = acc[i][2]; c.w = acc[i][3];
        if (EPI >= 1) { c.x += bv.x; c.y += bv.y; c.z += bv.z; c.w += bv.w; }
        if (EPI == 1) {
            c.x = c.x > 0.f ? c.x : expm1f(c.x);
            c.y = c.y > 0.f ? c.y : expm1f(c.y);
            c.z = c.z > 0.f ? c.z : expm1f(c.z);
            c.w = c.w > 0.f ? c.w : expm1f(c.w);
        }
        *(float4*)(C + (size_t)gm * Nc + gn0) = c;
    }
}

// ---------------- fused attention GEMM: beta += sum tanh(z@W^T + b) * att ------
__global__ __launch_bounds__(256)
void gemm_att_kernel(const float* __restrict__ A, const float* __restrict__ W,
                     const float* __restrict__ bias, const float* __restrict__ att,
                     float* __restrict__ beta_out, int M, int K)
{
    __shared__ float As[BKK][BM];
    __shared__ float Ws[BKK][BN];

    const int tid  = threadIdx.x;
    const int bm   = blockIdx.y * BM;
    const int bn   = blockIdx.x * BN;
    const int tx   = tid & 15;
    const int ty   = tid >> 4;
    const int lrow = tid >> 2;
    const int lq   = (tid & 3) * 4;

    float acc[4][4] = {};

    for (int k0 = 0; k0 < K; k0 += BKK) {
        float4 av = make_float4(0.f, 0.f, 0.f, 0.f);
        int gm = bm + lrow;
        if (gm < M && (k0 + lq) < K)
            av = *(const float4*)(A + (size_t)gm * K + k0 + lq);
        As[lq + 0][lrow] = av.x; As[lq + 1][lrow] = av.y;
        As[lq + 2][lrow] = av.z; As[lq + 3][lrow] = av.w;

        float4 wv = make_float4(0.f, 0.f, 0.f, 0.f);
        int gn = bn + lrow;
        if ((k0 + lq) < K)
            wv = *(const float4*)(W + (size_t)gn * K + k0 + lq);
        Ws[lq + 0][lrow] = wv.x; Ws[lq + 1][lrow] = wv.y;
        Ws[lq + 2][lrow] = wv.z; Ws[lq + 3][lrow] = wv.w;

        __syncthreads();
#pragma unroll
        for (int k = 0; k < BKK; ++k) {
            float4 a4 = *(const float4*)(&As[k][ty << 2]);
            float4 b4 = *(const float4*)(&Ws[k][tx << 2]);
            float a[4] = {a4.x, a4.y, a4.z, a4.w};
            float b[4] = {b4.x, b4.y, b4.z, b4.w};
#pragma unroll
            for (int i = 0; i < 4; ++i)
#pragma unroll
                for (int j = 0; j < 4; ++j)
                    acc[i][j] += a[i] * b[j];
        }
        __syncthreads();
    }

    const int gm0 = bm + (ty << 2);
    const int gn0 = bn + (tx << 2);
    float s = 0.f;
#pragma unroll
    for (int i = 0; i < 4; ++i) {
        int gm = gm0 + i;
        if (gm >= M) break;
#pragma unroll
        for (int j = 0; j < 4; ++j) {
            float t = tanhf(acc[i][j] + bias[gn0 + j]);
            s += t * att[gn0 + j];
        }
    }
    __shared__ float red[256];
    red[tid] = s;
    __syncthreads();
    for (int o = 128; o > 0; o >>= 1) {
        if (tid < o) red[tid] += red[tid + o];
        __syncthreads();
    }
    if (tid == 0) atomicAdd(beta_out, red[0]);
}

// ---------------- SpMM scatter: z[dst] += val * ft[src]  (vector RED) ----------
__global__ __launch_bounds__(256)
void spmm_kernel(const float4* __restrict__ ft, const int* __restrict__ src,
                 const int* __restrict__ dst, const float* __restrict__ vals,
                 float4* __restrict__ z)
{
    int gid = blockIdx.x * blockDim.x + threadIdx.x;
    if (gid >= EE * 64) return;
    int e = gid >> 6;
    int c = gid & 63;
    int s = src[e];
    int d = dst[e];
    float v = vals[e];
    float4 f = ft[(size_t)s * 64 + c];
    float4* p = &z[(size_t)d * 64 + c];
    asm volatile("red.global.add.v4.f32 [%0], {%1,%2,%3,%4};"
                 :: "l"(p), "f"(v * f.x), "f"(v * f.y), "f"(v * f.z), "f"(v * f.w)
                 : "memory");
}

// ---------------- z = prelu(z + b_gcn[view], a_gcn[view]) ----------------------
__global__ __launch_bounds__(256)
void bias_prelu_kernel(float4* __restrict__ z, const float* __restrict__ b,
                       const float* __restrict__ a_ptr)
{
    int i = blockIdx.x * blockDim.x + threadIdx.x;
    if (i >= NN * 64) return;
    float a = *a_ptr;
    float4 bv = *(const float4*)(b + ((i & 63) << 2));
    float4 x = z[i];
    x.x += bv.x; x.y += bv.y; x.z += bv.z; x.w += bv.w;
    x.x = x.x >= 0.f ? x.x : a * x.x;
    x.y = x.y >= 0.f ? x.y : a * x.y;
    x.z = x.z >= 0.f ? x.z : a * x.z;
    x.w = x.w >= 0.f ? x.w : a * x.w;
    z[i] = x;
}

// ---------------- BN column stats -----------------------------------------------
__global__ __launch_bounds__(256)
void colstats_kernel(const float* __restrict__ x, float* __restrict__ stats)
{
    int c = blockIdx.x * 256 + threadIdx.x;   // gridDim.x = 2 -> 512 cols
    float s = 0.f, sq = 0.f;
    for (int r = blockIdx.y; r < NN; r += gridDim.y) {
        float v = x[(size_t)r * PHH + c];
        s += v;
        sq += v * v;
    }
    atomicAdd(&stats[c], s);
    atomicAdd(&stats[PHH + c], sq);
}

// ---------------- BN + PReLU in place -------------------------------------------
__global__ __launch_bounds__(256)
void bn_prelu_kernel(float4* __restrict__ x, const float* __restrict__ stats,
                     const float* __restrict__ g, const float* __restrict__ b,
                     const float* __restrict__ a_ptr)
{
    int i = blockIdx.x * blockDim.x + threadIdx.x;
    if (i >= NN * (PHH / 4)) return;
    int c = (i & (PHH / 4 - 1)) << 2;
    float a = *a_ptr;
    float4 sm = *(const float4*)(stats + c);
    float4 sq = *(const float4*)(stats + PHH + c);
    float4 gv = *(const float4*)(g + c);
    float4 bv = *(const float4*)(b + c);
    float4 v = x[i];
    float invN = 1.f / (float)NN;

    float mu, var, sc, sh, y;
    mu = sm.x * invN; var = sq.x * invN - mu * mu; sc = gv.x * rsqrtf(var + BN_EPS);
    sh = bv.x - mu * sc; y = v.x * sc + sh; v.x = y >= 0.f ? y : a * y;
    mu = sm.y * invN; var = sq.y * invN - mu * mu; sc = gv.y * rsqrtf(var + BN_EPS);
    sh = bv.y - mu * sc; y = v.y * sc + sh; v.y = y >= 0.f ? y : a * y;
    mu = sm.z * invN; var = sq.z * invN - mu * mu; sc = gv.z * rsqrtf(var + BN_EPS);
    sh = bv.z - mu * sc; y = v.z * sc + sh; v.z = y >= 0.f ? y : a * y;
    mu = sm.w * invN; var = sq.w * invN - mu * mu; sc = gv.w * rsqrtf(var + BN_EPS);
    sh = bv.w - mu * sc; y = v.w * sc + sh; v.w = y >= 0.f ? y : a * y;
    x[i] = v;
}

// ---------------- cosine loss accumulation (one warp per node) ------------------
__global__ __launch_bounds__(256)
void loss_kernel(const float4* __restrict__ p, const float4* __restrict__ t1,
                 const float4* __restrict__ t2, float* __restrict__ acc)
{
    int gid  = blockIdx.x * blockDim.x + threadIdx.x;
    int node = gid >> 5;
    int lane = gid & 31;
    float pp = 0.f, n1 = 0.f, n2 = 0.f, d1 = 0.f, d2 = 0.f;
    if (node < NN) {
        size_t base = (size_t)node * 64;
#pragma unroll
        for (int r = 0; r < 2; ++r) {
            float4 a  = p [base + lane + 32 * r];
            float4 b  = t1[base + lane + 32 * r];
            float4 cc = t2[base + lane + 32 * r];
            pp += a.x * a.x + a.y * a.y + a.z * a.z + a.w * a.w;
            n1 += b.x * b.x + b.y * b.y + b.z * b.z + b.w * b.w;
            n2 += cc.x * cc.x + cc.y * cc.y + cc.z * cc.z + cc.w * cc.w;
            d1 += a.x * b.x + a.y * b.y + a.z * b.z + a.w * b.w;
            d2 += a.x * cc.x + a.y * cc.y + a.z * cc.z + a.w * cc.w;
        }
    }
#pragma unroll
    for (int o = 16; o > 0; o >>= 1) {
        pp += __shfl_down_sync(0xffffffffu, pp, o);
        n1 += __shfl_down_sync(0xffffffffu, n1, o);
        n2 += __shfl_down_sync(0xffffffffu, n2, o);
        d1 += __shfl_down_sync(0xffffffffu, d1, o);
        d2 += __shfl_down_sync(0xffffffffu, d2, o);
    }
    __shared__ float sacc[8];
    float contrib = 0.f;
    if (lane == 0 && node < NN) {
        float np  = fmaxf(sqrtf(pp), 1e-12f);
        float nn1 = fmaxf(sqrtf(n1), 1e-12f);
        float nn2 = fmaxf(sqrtf(n2), 1e-12f);
        contrib = d1 / (np * nn1) + d2 / (np * nn2);
    }
    int wid = threadIdx.x >> 5;
    if (lane == 0) sacc[wid] = contrib;
    __syncthreads();
    if (threadIdx.x == 0) {
        float s = 0.f;
#pragma unroll
        for (int i = 0; i < 8; ++i) s += sacc[i];
        atomicAdd(acc, s);
    }
}

// ---------------- finalize: softmax(beta), loss --------------------------------
__global__ void finalize_kernel(float* __restrict__ out_loss, int write_loss)
{
    float invN = 1.f / (float)NN;
    float b0 = g_beta_raw[0] * invN;
    float b1 = g_beta_raw[1] * invN;
    float b2 = g_beta_raw[2] * invN;
    float m = fmaxf(b0, fmaxf(b1, b2));
    float e0 = expf(b0 - m), e1 = expf(b1 - m), e2 = expf(b2 - m);
    float s = e0 + e1 + e2;
    g_beta[0] = e0 / s;   // teacher view1
    g_beta[1] = e1 / s;   // teacher view2
    g_beta[2] = e2 / s;   // student view0
    if (write_loss) *out_loss = 2.0f - g_loss_acc * invN;
}

// ---------------- z_out = b0*z1 + b1*z2 + b2*z0 ---------------------------------
__global__ __launch_bounds__(256)
void zout_kernel(float4* __restrict__ out, const float4* __restrict__ z1,
                 const float4* __restrict__ z2, const float4* __restrict__ z0)
{
    int i = blockIdx.x * blockDim.x + threadIdx.x;
    if (i >= NN * 64) return;
    float b0 = g_beta[0], b1 = g_beta[1], b2 = g_beta[2];
    float4 a = z1[i], b = z2[i], c = z0[i];
    float4 r;
    r.x = b0 * a.x + b1 * b.x + b2 * c.x;
    r.y = b0 * a.y + b1 * b.y + b2 * c.y;
    r.z = b0 * a.z + b1 * b.z + b2 * c.z;
    r.w = b0 * a.w + b1 * b.w + b2 * c.w;
    out[i] = r;
}

// ---------------- host ----------------------------------------------------------
extern "C" void kernel_launch(void* const* d_in, const int* in_sizes, int n_in,
                              void* d_out, int out_size)
{
    const float* feats   = (const float*)d_in[0];
    const int*   src     = (const int*)  d_in[1];
    const int*   dst     = (const int*)  d_in[2];
    const float* vals    = (const float*)d_in[3];
    const float* W_trans = (const float*)d_in[4];
    const float* b_trans = (const float*)d_in[5];
    const float* W_gcn   = (const float*)d_in[6];
    const float* b_gcn   = (const float*)d_in[7];
    const float* a_gcn   = (const float*)d_in[8];
    const float* W1      = (const float*)d_in[9];
    const float* b1      = (const float*)d_in[10];
    const float* bn_g    = (const float*)d_in[11];
    const float* bn_b    = (const float*)d_in[12];
    const float* a_pred  = (const float*)d_in[13];
    const float* W2      = (const float*)d_in[14];
    const float* b2      = (const float*)d_in[15];
    const float* W_att   = (const float*)d_in[16];
    const float* b_att   = (const float*)d_in[17];
    const float* att     = (const float*)d_in[18];

    float *h, *ft, *z0, *z1, *z2, *x, *vp, *stats, *beta_raw, *loss_acc;
    cudaGetSymbolAddress((void**)&h,  g_h);
    cudaGetSymbolAddress((void**)&ft, g_ft);
    cudaGetSymbolAddress((void**)&z0, g_z0);
    cudaGetSymbolAddress((void**)&z1, g_z1);
    cudaGetSymbolAddress((void**)&z2, g_z2);
    cudaGetSymbolAddress((void**)&x,  g_x);
    cudaGetSymbolAddress((void**)&vp, g_vp);
    cudaGetSymbolAddress((void**)&stats,    g_stats);
    cudaGetSymbolAddress((void**)&beta_raw, g_beta_raw);
    cudaGetSymbolAddress((void**)&loss_acc, g_loss_acc);

    const size_t zbytes = (size_t)NN * HH * sizeof(float);
    cudaMemsetAsync(z0, 0, zbytes);
    cudaMemsetAsync(z1, 0, zbytes);
    cudaMemsetAsync(z2, 0, zbytes);
    cudaMemsetAsync(stats, 0, 2 * PHH * sizeof(float));
    cudaMemsetAsync(beta_raw, 0, 3 * sizeof(float));
    cudaMemsetAsync(loss_acc, 0, sizeof(float));

    const int mb = (NN + BM - 1) / BM;   // 782

    // h = elu(feats @ W_trans^T + b_trans)
    gemm_tn_kernel<1><<<dim3(HH / BN, mb), 256>>>(feats, W_trans, b_trans, h, NN, HH, FEATD);

    // three GCN views
    float* zs[3] = {z0, z1, z2};
    for (int v = 0; v < PP; ++v) {
        gemm_tn_kernel<0><<<dim3(HH / BN, mb), 256>>>(h, W_gcn + (size_t)v * HH * HH,
                                                      nullptr, ft, NN, HH, HH);
        spmm_kernel<<<(EE * 64) / 256, 256>>>((const float4*)ft, src + (size_t)v * EE,
                                              dst + (size_t)v * EE, vals + (size_t)v * EE,
                                              (float4*)zs[v]);
        bias_prelu_kernel<<<(NN * 64) / 256, 256>>>((float4*)zs[v], b_gcn + (size_t)v * HH,
                                                    a_gcn + v);
    }

    // student predictor
    gemm_tn_kernel<2><<<dim3(PHH / BN, mb), 256>>>(z0, W1, b1, x, NN, PHH, HH);
    colstats_kernel<<<dim3(2, 512), 256>>>(x, stats);
    bn_prelu_kernel<<<(NN * PHH / 4) / 256, 256>>>((float4*)x, stats, bn_g, bn_b, a_pred);
    gemm_tn_kernel<2><<<dim3(HH / BN, mb), 256>>>(x, W2, b2, vp, NN, HH, PHH);

    // cosine losses vs teachers (views 1 and 2)
    loss_kernel<<<(NN * 32) / 256, 256>>>((const float4*)vp, (const float4*)z1,
                                          (const float4*)z2, loss_acc);

    // type-level attention: z_sum order = [teacher1, teacher2, student]
    gemm_att_kernel<<<dim3(HH / BN, mb), 256>>>(z1, W_att, b_att, att, beta_raw + 0, NN, HH);
    gemm_att_kernel<<<dim3(HH / BN, mb), 256>>>(z2, W_att, b_att, att, beta_raw + 1, NN, HH);
    gemm_att_kernel<<<dim3(HH / BN, mb), 256>>>(z0, W_att, b_att, att, beta_raw + 2, NN, HH);

    float* outf = (float*)d_out;
    int write_loss = (out_size > NN * HH) ? 1 : 0;
    finalize_kernel<<<1, 1>>>(outf + (size_t)NN * HH, write_loss);
    zout_kernel<<<(NN * 64) / 256, 256>>>((float4*)outf, (const float4*)z1,
                                          (const float4*)z2, (const float4*)z0);
}

// round 3
// speedup vs baseline: 1.6669x; 1.6669x over previous
#include <cuda_runtime.h>
#include <math.h>
#include <stdint.h>

// ---------------- problem constants ----------------
#define NN   50000
#define PP   3
#define EE   800000
#define FEATD 1000
#define HH   256
#define PHH  512
#define BN_EPS 1e-5f

// ---------------- device scratch (no allocations allowed) ----------------
__device__ float g_h [(size_t)NN * HH];
__device__ float g_ft[(size_t)NN * HH];
__device__ float g_z0[(size_t)NN * HH];
__device__ float g_z1[(size_t)NN * HH];
__device__ float g_z2[(size_t)NN * HH];
__device__ float g_x [(size_t)NN * PHH];
__device__ float g_vp[(size_t)NN * HH];
__device__ float g_stats[2 * PHH];
__device__ float g_beta_raw[3];
__device__ float g_beta[3];
__device__ float g_loss_acc;

// ---------------- tf32 helpers ---------------------------------------------------
__device__ __forceinline__ void mma_tf32(float* c, const uint32_t* a, const uint32_t* b)
{
    asm volatile(
        "mma.sync.aligned.m16n8k8.row.col.f32.tf32.tf32.f32 "
        "{%0,%1,%2,%3}, {%4,%5,%6,%7}, {%8,%9}, {%0,%1,%2,%3};\n"
        : "+f"(c[0]), "+f"(c[1]), "+f"(c[2]), "+f"(c[3])
        : "r"(a[0]), "r"(a[1]), "r"(a[2]), "r"(a[3]), "r"(b[0]), "r"(b[1]));
}

__device__ __forceinline__ uint32_t f2tf32(float x)
{
    uint32_t r;
    asm("cvt.rna.tf32.f32 %0, %1;" : "=r"(r) : "f"(x));
    return r;
}

// ---------------- tf32 GEMM: C[M,Nc] = act(A[M,K] @ W[Nc,K]^T + bias) -----------
// Block tile 128x64, BK=32, 8 warps (warp tile 32x32 = 2x4 m16n8k8).
// SPLITV=1 -> 3xTF32 error-compensated (fp32-grade accuracy).
#define TBM 128
#define TBN 64
#define TSTR 36   // padded smem stride (floats)

#define GEMM_TF32_MAINLOOP(SPLITV)                                                  \
    __shared__ float As[TBM][TSTR];                                                 \
    __shared__ float Ws[TBN][TSTR];                                                 \
    const int tid  = threadIdx.x;                                                   \
    const int wid  = tid >> 5;                                                      \
    const int lane = tid & 31;                                                      \
    const int g    = lane >> 2;                                                     \
    const int t    = lane & 3;                                                      \
    const int wm   = (wid & 3) << 5;                                                \
    const int wn   = (wid >> 2) << 5;                                               \
    const int bm   = blockIdx.y * TBM;                                              \
    const int bn   = blockIdx.x * TBN;                                              \
    float acc[2][4][4] = {};                                                        \
    for (int k0 = 0; k0 < K; k0 += 32) {                                            \
        _Pragma("unroll")                                                           \
        for (int q = 0; q < 4; ++q) {                                               \
            int idx = tid + (q << 8);                                               \
            int r = idx >> 3, c4 = (idx & 7) << 2;                                  \
            float4 v = make_float4(0.f, 0.f, 0.f, 0.f);                             \
            int gm = bm + r;                                                        \
            if (gm < M && (k0 + c4) < K)                                            \
                v = *(const float4*)(A + (size_t)gm * K + k0 + c4);                 \
            *(float4*)&As[r][c4] = v;                                               \
        }                                                                           \
        _Pragma("unroll")                                                           \
        for (int q = 0; q < 2; ++q) {                                               \
            int idx = tid + (q << 8);                                               \
            int r = idx >> 3, c4 = (idx & 7) << 2;                                  \
            float4 v = make_float4(0.f, 0.f, 0.f, 0.f);                             \
            if ((k0 + c4) < K)                                                      \
                v = *(const float4*)(W + (size_t)(bn + r) * K + k0 + c4);           \
            *(float4*)&Ws[r][c4] = v;                                               \
        }                                                                           \
        __syncthreads();                                                            \
        _Pragma("unroll")                                                           \
        for (int ks = 0; ks < 4; ++ks) {                                            \
            int kk = ks << 3;                                                       \
            float afv[2][4], bfv[4][2];                                             \
            _Pragma("unroll")                                                       \
            for (int i = 0; i < 2; ++i) {                                           \
                int rb = wm + (i << 4);                                             \
                afv[i][0] = As[rb + g    ][kk + t    ];                             \
                afv[i][1] = As[rb + g + 8][kk + t    ];                             \
                afv[i][2] = As[rb + g    ][kk + t + 4];                             \
                afv[i][3] = As[rb + g + 8][kk + t + 4];                             \
            }                                                                       \
            _Pragma("unroll")                                                       \
            for (int j = 0; j < 4; ++j) {                                           \
                int nb = wn + (j << 3);                                             \
                bfv[j][0] = Ws[nb + g][kk + t    ];                                 \
                bfv[j][1] = Ws[nb + g][kk + t + 4];                                 \
            }                                                                       \
            uint32_t ab[2][4], bb[4][2];                                            \
            _Pragma("unroll")                                                       \
            for (int i = 0; i < 2; ++i)                                             \
                _Pragma("unroll")                                                   \
                for (int e = 0; e < 4; ++e) ab[i][e] = f2tf32(afv[i][e]);           \
            _Pragma("unroll")                                                       \
            for (int j = 0; j < 4; ++j)                                             \
                _Pragma("unroll")                                                   \
                for (int e = 0; e < 2; ++e) bb[j][e] = f2tf32(bfv[j][e]);           \
            if (SPLITV) {                                                           \
                uint32_t asm_[2][4], bsm[4][2];                                     \
                _Pragma("unroll")                                                   \
                for (int i = 0; i < 2; ++i)                                         \
                    _Pragma("unroll")                                               \
                    for (int e = 0; e < 4; ++e)                                     \
                        asm_[i][e] = f2tf32(afv[i][e] - __uint_as_float(ab[i][e])); \
                _Pragma("unroll")                                                   \
                for (int j = 0; j < 4; ++j)                                         \
                    _Pragma("unroll")                                               \
                    for (int e = 0; e < 2; ++e)                                     \
                        bsm[j][e] = f2tf32(bfv[j][e] - __uint_as_float(bb[j][e]));  \
                _Pragma("unroll")                                                   \
                for (int i = 0; i < 2; ++i)                                         \
                    _Pragma("unroll")                                               \
                    for (int j = 0; j < 4; ++j) {                                   \
                        mma_tf32(acc[i][j], asm_[i], bb[j]);                        \
                        mma_tf32(acc[i][j], ab[i], bsm[j]);                         \
                    }                                                               \
            }                                                                       \
            _Pragma("unroll")                                                       \
            for (int i = 0; i < 2; ++i)                                             \
                _Pragma("unroll")                                                   \
                for (int j = 0; j < 4; ++j)                                         \
                    mma_tf32(acc[i][j], ab[i], bb[j]);                              \
        }                                                                           \
        __syncthreads();                                                            \
    }

// EPI: 0 = raw, 1 = bias+ELU, 2 = bias
template<int EPI, int SPLITV>
__global__ __launch_bounds__(256, 2)
void gemm_tf32_kernel(const float* __restrict__ A, const float* __restrict__ W,
                      const float* __restrict__ bias, float* __restrict__ C,
                      int M, int Nc, int K)
{
    GEMM_TF32_MAINLOOP(SPLITV);

#pragma unroll
    for (int i = 0; i < 2; ++i) {
#pragma unroll
        for (int j = 0; j < 4; ++j) {
            int r0 = bm + wm + (i << 4) + g;
            int r1 = r0 + 8;
            int c0 = bn + wn + (j << 3) + (t << 1);
            float bx = 0.f, by = 0.f;
            if (EPI >= 1) { bx = bias[c0]; by = bias[c0 + 1]; }
            float v0 = acc[i][j][0], v1 = acc[i][j][1];
            float v2 = acc[i][j][2], v3 = acc[i][j][3];
            if (EPI >= 1) { v0 += bx; v1 += by; v2 += bx; v3 += by; }
            if (EPI == 1) {
                v0 = v0 > 0.f ? v0 : expm1f(v0);
                v1 = v1 > 0.f ? v1 : expm1f(v1);
                v2 = v2 > 0.f ? v2 : expm1f(v2);
                v3 = v3 > 0.f ? v3 : expm1f(v3);
            }
            if (r0 < M) *(float2*)(C + (size_t)r0 * Nc + c0) = make_float2(v0, v1);
            if (r1 < M) *(float2*)(C + (size_t)r1 * Nc + c0) = make_float2(v2, v3);
        }
    }
}

// fused attention GEMM: beta += sum over tile of tanh(z@W^T + b) * att
__global__ __launch_bounds__(256, 2)
void gemm_att_tf32_kernel(const float* __restrict__ A, const float* __restrict__ W,
                          const float* __restrict__ bias, const float* __restrict__ att,
                          float* __restrict__ beta_out, int M, int K)
{
    const int Nc = HH; (void)Nc;
    GEMM_TF32_MAINLOOP(0);

    float s = 0.f;
#pragma unroll
    for (int i = 0; i < 2; ++i) {
#pragma unroll
        for (int j = 0; j < 4; ++j) {
            int r0 = bm + wm + (i << 4) + g;
            int r1 = r0 + 8;
            int c0 = bn + wn + (j << 3) + (t << 1);
            float bx = bias[c0], by = bias[c0 + 1];
            float ax = att[c0],  ay = att[c0 + 1];
            if (r0 < M) s += tanhf(acc[i][j][0] + bx) * ax + tanhf(acc[i][j][1] + by) * ay;
            if (r1 < M) s += tanhf(acc[i][j][2] + bx) * ax + tanhf(acc[i][j][3] + by) * ay;
        }
    }
    __shared__ float red[256];
    red[tid] = s;
    __syncthreads();
    for (int o = 128; o > 0; o >>= 1) {
        if (tid < o) red[tid] += red[tid + o];
        __syncthreads();
    }
    if (tid == 0) atomicAdd(beta_out, red[0]);
}

// ---------------- SpMM scatter: z[dst] += val * ft[src]  (vector RED) ----------
__global__ __launch_bounds__(256)
void spmm_kernel(const float4* __restrict__ ft, const int* __restrict__ src,
                 const int* __restrict__ dst, const float* __restrict__ vals,
                 float4* __restrict__ z)
{
    int gid = blockIdx.x * blockDim.x + threadIdx.x;
    if (gid >= EE * 64) return;
    int e = gid >> 6;
    int c = gid & 63;
    int s = src[e];
    int d = dst[e];
    float v = vals[e];
    float4 f = ft[(size_t)s * 64 + c];
    float4* p = &z[(size_t)d * 64 + c];
    asm volatile("red.global.add.v4.f32 [%0], {%1,%2,%3,%4};"
                 :: "l"(p), "f"(v * f.x), "f"(v * f.y), "f"(v * f.z), "f"(v * f.w)
                 : "memory");
}

// ---------------- z = prelu(z + b_gcn[view], a_gcn[view]) ----------------------
__global__ __launch_bounds__(256)
void bias_prelu_kernel(float4* __restrict__ z, const float* __restrict__ b,
                       const float* __restrict__ a_ptr)
{
    int i = blockIdx.x * blockDim.x + threadIdx.x;
    if (i >= NN * 64) return;
    float a = *a_ptr;
    float4 bv = *(const float4*)(b + ((i & 63) << 2));
    float4 x = z[i];
    x.x += bv.x; x.y += bv.y; x.z += bv.z; x.w += bv.w;
    x.x = x.x >= 0.f ? x.x : a * x.x;
    x.y = x.y >= 0.f ? x.y : a * x.y;
    x.z = x.z >= 0.f ? x.z : a * x.z;
    x.w = x.w >= 0.f ? x.w : a * x.w;
    z[i] = x;
}

// ---------------- BN column stats -----------------------------------------------
__global__ __launch_bounds__(256)
void colstats_kernel(const float* __restrict__ x, float* __restrict__ stats)
{
    int c = blockIdx.x * 256 + threadIdx.x;
    float s = 0.f, sq = 0.f;
    for (int r = blockIdx.y; r < NN; r += gridDim.y) {
        float v = x[(size_t)r * PHH + c];
        s += v;
        sq += v * v;
    }
    atomicAdd(&stats[c], s);
    atomicAdd(&stats[PHH + c], sq);
}

// ---------------- BN + PReLU in place -------------------------------------------
__global__ __launch_bounds__(256)
void bn_prelu_kernel(float4* __restrict__ x, const float* __restrict__ stats,
                     const float* __restrict__ g, const float* __restrict__ b,
                     const float* __restrict__ a_ptr)
{
    int i = blockIdx.x * blockDim.x + threadIdx.x;
    if (i >= NN * (PHH / 4)) return;
    int c = (i & (PHH / 4 - 1)) << 2;
    float a = *a_ptr;
    float4 sm = *(const float4*)(stats + c);
    float4 sq = *(const float4*)(stats + PHH + c);
    float4 gv = *(const float4*)(g + c);
    float4 bv = *(const float4*)(b + c);
    float4 v = x[i];
    float invN = 1.f / (float)NN;

    float mu, var, sc, sh, y;
    mu = sm.x * invN; var = sq.x * invN - mu * mu; sc = gv.x * rsqrtf(var + BN_EPS);
    sh = bv.x - mu * sc; y = v.x * sc + sh; v.x = y >= 0.f ? y : a * y;
    mu = sm.y * invN; var = sq.y * invN - mu * mu; sc = gv.y * rsqrtf(var + BN_EPS);
    sh = bv.y - mu * sc; y = v.y * sc + sh; v.y = y >= 0.f ? y : a * y;
    mu = sm.z * invN; var = sq.z * invN - mu * mu; sc = gv.z * rsqrtf(var + BN_EPS);
    sh = bv.z - mu * sc; y = v.z * sc + sh; v.z = y >= 0.f ? y : a * y;
    mu = sm.w * invN; var = sq.w * invN - mu * mu; sc = gv.w * rsqrtf(var + BN_EPS);
    sh = bv.w - mu * sc; y = v.w * sc + sh; v.w = y >= 0.f ? y : a * y;
    x[i] = v;
}

// ---------------- cosine loss accumulation (one warp per node) ------------------
__global__ __launch_bounds__(256)
void loss_kernel(const float4* __restrict__ p, const float4* __restrict__ t1,
                 const float4* __restrict__ t2, float* __restrict__ acc)
{
    int gid  = blockIdx.x * blockDim.x + threadIdx.x;
    int node = gid >> 5;
    int lane = gid & 31;
    float pp = 0.f, n1 = 0.f, n2 = 0.f, d1 = 0.f, d2 = 0.f;
    if (node < NN) {
        size_t base = (size_t)node * 64;
#pragma unroll
        for (int r = 0; r < 2; ++r) {
            float4 a  = p [base + lane + 32 * r];
            float4 b  = t1[base + lane + 32 * r];
            float4 cc = t2[base + lane + 32 * r];
            pp += a.x * a.x + a.y * a.y + a.z * a.z + a.w * a.w;
            n1 += b.x * b.x + b.y * b.y + b.z * b.z + b.w * b.w;
            n2 += cc.x * cc.x + cc.y * cc.y + cc.z * cc.z + cc.w * cc.w;
            d1 += a.x * b.x + a.y * b.y + a.z * b.z + a.w * b.w;
            d2 += a.x * cc.x + a.y * cc.y + a.z * cc.z + a.w * cc.w;
        }
    }
#pragma unroll
    for (int o = 16; o > 0; o >>= 1) {
        pp += __shfl_down_sync(0xffffffffu, pp, o);
        n1 += __shfl_down_sync(0xffffffffu, n1, o);
        n2 += __shfl_down_sync(0xffffffffu, n2, o);
        d1 += __shfl_down_sync(0xffffffffu, d1, o);
        d2 += __shfl_down_sync(0xffffffffu, d2, o);
    }
    __shared__ float sacc[8];
    float contrib = 0.f;
    if (lane == 0 && node < NN) {
        float np  = fmaxf(sqrtf(pp), 1e-12f);
        float nn1 = fmaxf(sqrtf(n1), 1e-12f);
        float nn2 = fmaxf(sqrtf(n2), 1e-12f);
        contrib = d1 / (np * nn1) + d2 / (np * nn2);
    }
    int wid = threadIdx.x >> 5;
    if (lane == 0) sacc[wid] = contrib;
    __syncthreads();
    if (threadIdx.x == 0) {
        float s = 0.f;
#pragma unroll
        for (int i = 0; i < 8; ++i) s += sacc[i];
        atomicAdd(acc, s);
    }
}

// ---------------- finalize: softmax(beta), loss --------------------------------
__global__ void finalize_kernel(float* __restrict__ out_loss, int write_loss)
{
    float invN = 1.f / (float)NN;
    float b0 = g_beta_raw[0] * invN;
    float b1 = g_beta_raw[1] * invN;
    float b2 = g_beta_raw[2] * invN;
    float m = fmaxf(b0, fmaxf(b1, b2));
    float e0 = expf(b0 - m), e1 = expf(b1 - m), e2 = expf(b2 - m);
    float s = e0 + e1 + e2;
    g_beta[0] = e0 / s;
    g_beta[1] = e1 / s;
    g_beta[2] = e2 / s;
    if (write_loss) *out_loss = 2.0f - g_loss_acc * invN;
}

// ---------------- z_out = b0*z1 + b1*z2 + b2*z0 ---------------------------------
__global__ __launch_bounds__(256)
void zout_kernel(float4* __restrict__ out, const float4* __restrict__ z1,
                 const float4* __restrict__ z2, const float4* __restrict__ z0)
{
    int i = blockIdx.x * blockDim.x + threadIdx.x;
    if (i >= NN * 64) return;
    float b0 = g_beta[0], b1 = g_beta[1], b2 = g_beta[2];
    float4 a = z1[i], b = z2[i], c = z0[i];
    float4 r;
    r.x = b0 * a.x + b1 * b.x + b2 * c.x;
    r.y = b0 * a.y + b1 * b.y + b2 * c.y;
    r.z = b0 * a.z + b1 * b.z + b2 * c.z;
    r.w = b0 * a.w + b1 * b.w + b2 * c.w;
    out[i] = r;
}

// ---------------- host ----------------------------------------------------------
extern "C" void kernel_launch(void* const* d_in, const int* in_sizes, int n_in,
                              void* d_out, int out_size)
{
    const float* feats   = (const float*)d_in[0];
    const int*   src     = (const int*)  d_in[1];
    const int*   dst     = (const int*)  d_in[2];
    const float* vals    = (const float*)d_in[3];
    const float* W_trans = (const float*)d_in[4];
    const float* b_trans = (const float*)d_in[5];
    const float* W_gcn   = (const float*)d_in[6];
    const float* b_gcn   = (const float*)d_in[7];
    const float* a_gcn   = (const float*)d_in[8];
    const float* W1      = (const float*)d_in[9];
    const float* b1      = (const float*)d_in[10];
    const float* bn_g    = (const float*)d_in[11];
    const float* bn_b    = (const float*)d_in[12];
    const float* a_pred  = (const float*)d_in[13];
    const float* W2      = (const float*)d_in[14];
    const float* b2      = (const float*)d_in[15];
    const float* W_att   = (const float*)d_in[16];
    const float* b_att   = (const float*)d_in[17];
    const float* att     = (const float*)d_in[18];

    float *h, *ft, *z0, *z1, *z2, *x, *vp, *stats, *beta_raw, *loss_acc;
    cudaGetSymbolAddress((void**)&h,  g_h);
    cudaGetSymbolAddress((void**)&ft, g_ft);
    cudaGetSymbolAddress((void**)&z0, g_z0);
    cudaGetSymbolAddress((void**)&z1, g_z1);
    cudaGetSymbolAddress((void**)&z2, g_z2);
    cudaGetSymbolAddress((void**)&x,  g_x);
    cudaGetSymbolAddress((void**)&vp, g_vp);
    cudaGetSymbolAddress((void**)&stats,    g_stats);
    cudaGetSymbolAddress((void**)&beta_raw, g_beta_raw);
    cudaGetSymbolAddress((void**)&loss_acc, g_loss_acc);

    const size_t zbytes = (size_t)NN * HH * sizeof(float);
    cudaMemsetAsync(z0, 0, zbytes);
    cudaMemsetAsync(z1, 0, zbytes);
    cudaMemsetAsync(z2, 0, zbytes);
    cudaMemsetAsync(stats, 0, 2 * PHH * sizeof(float));
    cudaMemsetAsync(beta_raw, 0, 3 * sizeof(float));
    cudaMemsetAsync(loss_acc, 0, sizeof(float));

    const int mb = (NN + TBM - 1) / TBM;   // 391

    // h = elu(feats @ W_trans^T + b_trans)   -- 3xTF32 (feeds everything)
    gemm_tf32_kernel<1, 1><<<dim3(HH / TBN, mb), 256>>>(feats, W_trans, b_trans, h,
                                                        NN, HH, FEATD);

    // three GCN views -- 3xTF32 (feed z_out directly)
    float* zs[3] = {z0, z1, z2};
    for (int v = 0; v < PP; ++v) {
        gemm_tf32_kernel<0, 1><<<dim3(HH / TBN, mb), 256>>>(h, W_gcn + (size_t)v * HH * HH,
                                                            nullptr, ft, NN, HH, HH);
        spmm_kernel<<<(EE * 64) / 256, 256>>>((const float4*)ft, src + (size_t)v * EE,
                                              dst + (size_t)v * EE, vals + (size_t)v * EE,
                                              (float4*)zs[v]);
        bias_prelu_kernel<<<(NN * 64) / 256, 256>>>((float4*)zs[v], b_gcn + (size_t)v * HH,
                                                    a_gcn + v);
    }

    // student predictor -- single-pass tf32 (feeds scalar loss only)
    gemm_tf32_kernel<2, 0><<<dim3(PHH / TBN, mb), 256>>>(z0, W1, b1, x, NN, PHH, HH);
    colstats_kernel<<<dim3(2, 512), 256>>>(x, stats);
    bn_prelu_kernel<<<(NN * PHH / 4) / 256, 256>>>((float4*)x, stats, bn_g, bn_b, a_pred);
    gemm_tf32_kernel<2, 0><<<dim3(HH / TBN, mb), 256>>>(x, W2, b2, vp, NN, HH, PHH);

    // cosine losses vs teachers (views 1 and 2)
    loss_kernel<<<(NN * 32) / 256, 256>>>((const float4*)vp, (const float4*)z1,
                                          (const float4*)z2, loss_acc);

    // type-level attention: z_sum order = [teacher1, teacher2, student]
    gemm_att_tf32_kernel<<<dim3(HH / TBN, mb), 256>>>(z1, W_att, b_att, att, beta_raw + 0, NN, HH);
    gemm_att_tf32_kernel<<<dim3(HH / TBN, mb), 256>>>(z2, W_att, b_att, att, beta_raw + 1, NN, HH);
    gemm_att_tf32_kernel<<<dim3(HH / TBN, mb), 256>>>(z0, W_att, b_att, att, beta_raw + 2, NN, HH);

    float* outf = (float*)d_out;
    int write_loss = (out_size > NN * HH) ? 1 : 0;
    finalize_kernel<<<1, 1>>>(outf + (size_t)NN * HH, write_loss);
    zout_kernel<<<(NN * 64) / 256, 256>>>((float4*)outf, (const float4*)z1,
                                          (const float4*)z2, (const float4*)z0);
}

// round 4
// speedup vs baseline: 1.7035x; 1.0220x over previous
#include <cuda_runtime.h>
#include <math.h>
#include <stdint.h>

// ---------------- problem constants ----------------
#define NN   50000
#define PP   3
#define EE   800000
#define FEATD 1000
#define HH   256
#define PHH  512
#define BN_EPS 1e-5f

// ---------------- device scratch (no allocations allowed) ----------------
__device__ float g_h [(size_t)NN * HH];        // elu(feats @ W_trans^T + b)
__device__ float g_ft[(size_t)NN * (3 * HH)];  // all 3 views' seq_fts [N, 768]
__device__ float g_z0[(size_t)NN * HH];
__device__ float g_z1[(size_t)NN * HH];
__device__ float g_z2[(size_t)NN * HH];
__device__ float g_x [(size_t)NN * PHH];
__device__ float g_vp[(size_t)NN * HH];
__device__ float g_stats[2 * PHH];
__device__ float g_beta_raw[3];
__device__ float g_beta[3];
__device__ float g_loss_acc;

// ---------------- tf32 helpers ---------------------------------------------------
__device__ __forceinline__ void mma_tf32(float* c, const uint32_t* a, const uint32_t* b)
{
    asm volatile(
        "mma.sync.aligned.m16n8k8.row.col.f32.tf32.tf32.f32 "
        "{%0,%1,%2,%3}, {%4,%5,%6,%7}, {%8,%9}, {%0,%1,%2,%3};\n"
        : "+f"(c[0]), "+f"(c[1]), "+f"(c[2]), "+f"(c[3])
        : "r"(a[0]), "r"(a[1]), "r"(a[2]), "r"(a[3]), "r"(b[0]), "r"(b[1]));
}

__device__ __forceinline__ uint32_t f2tf32(float x)
{
    uint32_t r;
    asm("cvt.rna.tf32.f32 %0, %1;" : "=r"(r) : "f"(x));
    return r;
}

__device__ __forceinline__ void cp16(uint32_t saddr, const void* gmem, bool pred)
{
    int sz = pred ? 16 : 0;
    asm volatile("cp.async.cg.shared.global [%0], [%1], 16, %2;\n"
                 :: "r"(saddr), "l"(gmem), "r"(sz));
}

// ---------------- tf32 GEMM (2-stage cp.async pipeline) -------------------------
// Block tile 128x64, BK=16, 8 warps (warp tile 32x32 = 2x4 m16n8k8).
// SPLITV=1 -> 3xTF32 error-compensated (fp32-grade accuracy).
#define TBM 128
#define TBN 64
#define BKP 16
#define TSTR 20   // padded smem stride (floats) -> conflict-free fragment LDS

#define GEMM_DECL()                                                                 \
    __shared__ float As[2][TBM][TSTR];                                              \
    __shared__ float Ws[2][TBN][TSTR];                                              \
    const int tid  = threadIdx.x;                                                   \
    const int wid  = tid >> 5;                                                      \
    const int lane = tid & 31;                                                      \
    const int g    = lane >> 2;                                                     \
    const int t    = lane & 3;                                                      \
    const int wm   = (wid & 3) << 5;                                                \
    const int wn   = (wid >> 2) << 5;                                               \
    const int bm   = blockIdx.y * TBM;                                              \
    const int bn   = blockIdx.x * TBN;                                              \
    const int ar0  = tid >> 2;                                                      \
    const int ar1  = ar0 + 64;                                                      \
    const int ac   = (tid & 3) << 2;                                                \
    float acc[2][4][4] = {};

#define GEMM_LOAD_STAGE(S, KO)                                                      \
    {                                                                               \
        int cc = (KO) + ac;                                                         \
        bool pv = (cc < K);                                                         \
        cp16((uint32_t)__cvta_generic_to_shared(&As[S][ar0][ac]),                   \
             A + (size_t)(bm + ar0) * K + cc, pv && (bm + ar0 < M));                \
        cp16((uint32_t)__cvta_generic_to_shared(&As[S][ar1][ac]),                   \
             A + (size_t)(bm + ar1) * K + cc, pv && (bm + ar1 < M));                \
        cp16((uint32_t)__cvta_generic_to_shared(&Ws[S][ar0][ac]),                   \
             W + (size_t)(bn + ar0) * K + cc, pv);                                  \
    }

#define GEMM_TF32_MAINLOOP(SPLITV)                                                  \
    GEMM_DECL();                                                                    \
    GEMM_LOAD_STAGE(0, 0);                                                          \
    asm volatile("cp.async.commit_group;\n" ::: "memory");                          \
    int buf = 0;                                                                    \
    for (int k0 = 0; k0 < K; k0 += BKP) {                                           \
        if (k0 + BKP < K) GEMM_LOAD_STAGE(buf ^ 1, k0 + BKP);                       \
        asm volatile("cp.async.commit_group;\n" ::: "memory");                      \
        asm volatile("cp.async.wait_group 1;\n" ::: "memory");                      \
        __syncthreads();                                                            \
        _Pragma("unroll")                                                           \
        for (int ks = 0; ks < 2; ++ks) {                                            \
            int kk = ks << 3;                                                       \
            float afv[2][4], bfv[4][2];                                             \
            _Pragma("unroll")                                                       \
            for (int i = 0; i < 2; ++i) {                                           \
                int rb = wm + (i << 4);                                             \
                afv[i][0] = As[buf][rb + g    ][kk + t    ];                        \
                afv[i][1] = As[buf][rb + g + 8][kk + t    ];                        \
                afv[i][2] = As[buf][rb + g    ][kk + t + 4];                        \
                afv[i][3] = As[buf][rb + g + 8][kk + t + 4];                        \
            }                                                                       \
            _Pragma("unroll")                                                       \
            for (int j = 0; j < 4; ++j) {                                           \
                int nb = wn + (j << 3);                                             \
                bfv[j][0] = Ws[buf][nb + g][kk + t    ];                            \
                bfv[j][1] = Ws[buf][nb + g][kk + t + 4];                            \
            }                                                                       \
            uint32_t ab[2][4], bb[4][2];                                            \
            _Pragma("unroll")                                                       \
            for (int i = 0; i < 2; ++i)                                             \
                _Pragma("unroll")                                                   \
                for (int e = 0; e < 4; ++e) ab[i][e] = f2tf32(afv[i][e]);           \
            _Pragma("unroll")                                                       \
            for (int j = 0; j < 4; ++j)                                             \
                _Pragma("unroll")                                                   \
                for (int e = 0; e < 2; ++e) bb[j][e] = f2tf32(bfv[j][e]);           \
            if (SPLITV) {                                                           \
                uint32_t asm_[2][4], bsm[4][2];                                     \
                _Pragma("unroll")                                                   \
                for (int i = 0; i < 2; ++i)                                         \
                    _Pragma("unroll")                                               \
                    for (int e = 0; e < 4; ++e)                                     \
                        asm_[i][e] = f2tf32(afv[i][e] - __uint_as_float(ab[i][e])); \
                _Pragma("unroll")                                                   \
                for (int j = 0; j < 4; ++j)                                         \
                    _Pragma("unroll")                                               \
                    for (int e = 0; e < 2; ++e)                                     \
                        bsm[j][e] = f2tf32(bfv[j][e] - __uint_as_float(bb[j][e]));  \
                _Pragma("unroll")                                                   \
                for (int i = 0; i < 2; ++i)                                         \
                    _Pragma("unroll")                                               \
                    for (int j = 0; j < 4; ++j) {                                   \
                        mma_tf32(acc[i][j], asm_[i], bb[j]);                        \
                        mma_tf32(acc[i][j], ab[i], bsm[j]);                         \
                    }                                                               \
            }                                                                       \
            _Pragma("unroll")                                                       \
            for (int i = 0; i < 2; ++i)                                             \
                _Pragma("unroll")                                                   \
                for (int j = 0; j < 4; ++j)                                         \
                    mma_tf32(acc[i][j], ab[i], bb[j]);                              \
        }                                                                           \
        __syncthreads();                                                            \
        buf ^= 1;                                                                   \
    }

// EPI: 0 = raw, 1 = bias+ELU, 2 = bias
template<int EPI, int SPLITV>
__global__ __launch_bounds__(256, 2)
void gemm_tf32_kernel(const float* __restrict__ A, const float* __restrict__ W,
                      const float* __restrict__ bias, float* __restrict__ C,
                      int M, int Nc, int K)
{
    GEMM_TF32_MAINLOOP(SPLITV);

#pragma unroll
    for (int i = 0; i < 2; ++i) {
#pragma unroll
        for (int j = 0; j < 4; ++j) {
            int r0 = bm + wm + (i << 4) + g;
            int r1 = r0 + 8;
            int c0 = bn + wn + (j << 3) + (t << 1);
            float bx = 0.f, by = 0.f;
            if (EPI >= 1) { bx = bias[c0]; by = bias[c0 + 1]; }
            float v0 = acc[i][j][0], v1 = acc[i][j][1];
            float v2 = acc[i][j][2], v3 = acc[i][j][3];
            if (EPI >= 1) { v0 += bx; v1 += by; v2 += bx; v3 += by; }
            if (EPI == 1) {
                v0 = v0 > 0.f ? v0 : expm1f(v0);
                v1 = v1 > 0.f ? v1 : expm1f(v1);
                v2 = v2 > 0.f ? v2 : expm1f(v2);
                v3 = v3 > 0.f ? v3 : expm1f(v3);
            }
            if (r0 < M) *(float2*)(C + (size_t)r0 * Nc + c0) = make_float2(v0, v1);
            if (r1 < M) *(float2*)(C + (size_t)r1 * Nc + c0) = make_float2(v2, v3);
        }
    }
}

// fused attention GEMM: beta += sum over tile of tanh(z@W^T + b) * att
__global__ __launch_bounds__(256, 2)
void gemm_att_tf32_kernel(const float* __restrict__ A, const float* __restrict__ W,
                          const float* __restrict__ bias, const float* __restrict__ att,
                          float* __restrict__ beta_out, int M, int K)
{
    GEMM_TF32_MAINLOOP(0);

    float s = 0.f;
#pragma unroll
    for (int i = 0; i < 2; ++i) {
#pragma unroll
        for (int j = 0; j < 4; ++j) {
            int r0 = bm + wm + (i << 4) + g;
            int r1 = r0 + 8;
            int c0 = bn + wn + (j << 3) + (t << 1);
            float bx = bias[c0], by = bias[c0 + 1];
            float ax = att[c0],  ay = att[c0 + 1];
            if (r0 < M) s += tanhf(acc[i][j][0] + bx) * ax + tanhf(acc[i][j][1] + by) * ay;
            if (r1 < M) s += tanhf(acc[i][j][2] + bx) * ax + tanhf(acc[i][j][3] + by) * ay;
        }
    }
    __shared__ float red[256];
    red[tid] = s;
    __syncthreads();
    for (int o = 128; o > 0; o >>= 1) {
        if (tid < o) red[tid] += red[tid + o];
        __syncthreads();
    }
    if (tid == 0) atomicAdd(beta_out, red[0]);
}

// ---------------- SpMM scatter: z[dst] += val * ft[src]  (vector RED) ----------
__global__ __launch_bounds__(256)
void spmm_kernel(const float4* __restrict__ ft, int stride4,
                 const int* __restrict__ src, const int* __restrict__ dst,
                 const float* __restrict__ vals, float4* __restrict__ z)
{
    int gid = blockIdx.x * blockDim.x + threadIdx.x;
    if (gid >= EE * 64) return;
    int e = gid >> 6;
    int c = gid & 63;
    int s = src[e];
    int d = dst[e];
    float v = vals[e];
    float4 f = ft[(size_t)s * stride4 + c];
    float4* p = &z[(size_t)d * 64 + c];
    asm volatile("red.global.add.v4.f32 [%0], {%1,%2,%3,%4};"
                 :: "l"(p), "f"(v * f.x), "f"(v * f.y), "f"(v * f.z), "f"(v * f.w)
                 : "memory");
}

// ---------------- z = prelu(z + b_gcn[view], a_gcn[view]) ----------------------
__global__ __launch_bounds__(256)
void bias_prelu_kernel(float4* __restrict__ z, const float* __restrict__ b,
                       const float* __restrict__ a_ptr)
{
    int i = blockIdx.x * blockDim.x + threadIdx.x;
    if (i >= NN * 64) return;
    float a = *a_ptr;
    float4 bv = *(const float4*)(b + ((i & 63) << 2));
    float4 x = z[i];
    x.x += bv.x; x.y += bv.y; x.z += bv.z; x.w += bv.w;
    x.x = x.x >= 0.f ? x.x : a * x.x;
    x.y = x.y >= 0.f ? x.y : a * x.y;
    x.z = x.z >= 0.f ? x.z : a * x.z;
    x.w = x.w >= 0.f ? x.w : a * x.w;
    z[i] = x;
}

// ---------------- BN column stats -----------------------------------------------
__global__ __launch_bounds__(256)
void colstats_kernel(const float* __restrict__ x, float* __restrict__ stats)
{
    int c = blockIdx.x * 256 + threadIdx.x;
    float s = 0.f, sq = 0.f;
    for (int r = blockIdx.y; r < NN; r += gridDim.y) {
        float v = x[(size_t)r * PHH + c];
        s += v;
        sq += v * v;
    }
    atomicAdd(&stats[c], s);
    atomicAdd(&stats[PHH + c], sq);
}

// ---------------- BN + PReLU in place -------------------------------------------
__global__ __launch_bounds__(256)
void bn_prelu_kernel(float4* __restrict__ x, const float* __restrict__ stats,
                     const float* __restrict__ g, const float* __restrict__ b,
                     const float* __restrict__ a_ptr)
{
    int i = blockIdx.x * blockDim.x + threadIdx.x;
    if (i >= NN * (PHH / 4)) return;
    int c = (i & (PHH / 4 - 1)) << 2;
    float a = *a_ptr;
    float4 sm = *(const float4*)(stats + c);
    float4 sq = *(const float4*)(stats + PHH + c);
    float4 gv = *(const float4*)(g + c);
    float4 bv = *(const float4*)(b + c);
    float4 v = x[i];
    float invN = 1.f / (float)NN;

    float mu, var, sc, sh, y;
    mu = sm.x * invN; var = sq.x * invN - mu * mu; sc = gv.x * rsqrtf(var + BN_EPS);
    sh = bv.x - mu * sc; y = v.x * sc + sh; v.x = y >= 0.f ? y : a * y;
    mu = sm.y * invN; var = sq.y * invN - mu * mu; sc = gv.y * rsqrtf(var + BN_EPS);
    sh = bv.y - mu * sc; y = v.y * sc + sh; v.y = y >= 0.f ? y : a * y;
    mu = sm.z * invN; var = sq.z * invN - mu * mu; sc = gv.z * rsqrtf(var + BN_EPS);
    sh = bv.z - mu * sc; y = v.z * sc + sh; v.z = y >= 0.f ? y : a * y;
    mu = sm.w * invN; var = sq.w * invN - mu * mu; sc = gv.w * rsqrtf(var + BN_EPS);
    sh = bv.w - mu * sc; y = v.w * sc + sh; v.w = y >= 0.f ? y : a * y;
    x[i] = v;
}

// ---------------- cosine loss accumulation (one warp per node) ------------------
__global__ __launch_bounds__(256)
void loss_kernel(const float4* __restrict__ p, const float4* __restrict__ t1,
                 const float4* __restrict__ t2, float* __restrict__ acc)
{
    int gid  = blockIdx.x * blockDim.x + threadIdx.x;
    int node = gid >> 5;
    int lane = gid & 31;
    float pp = 0.f, n1 = 0.f, n2 = 0.f, d1 = 0.f, d2 = 0.f;
    if (node < NN) {
        size_t base = (size_t)node * 64;
#pragma unroll
        for (int r = 0; r < 2; ++r) {
            float4 a  = p [base + lane + 32 * r];
            float4 b  = t1[base + lane + 32 * r];
            float4 cc = t2[base + lane + 32 * r];
            pp += a.x * a.x + a.y * a.y + a.z * a.z + a.w * a.w;
            n1 += b.x * b.x + b.y * b.y + b.z * b.z + b.w * b.w;
            n2 += cc.x * cc.x + cc.y * cc.y + cc.z * cc.z + cc.w * cc.w;
            d1 += a.x * b.x + a.y * b.y + a.z * b.z + a.w * b.w;
            d2 += a.x * cc.x + a.y * cc.y + a.z * cc.z + a.w * cc.w;
        }
    }
#pragma unroll
    for (int o = 16; o > 0; o >>= 1) {
        pp += __shfl_down_sync(0xffffffffu, pp, o);
        n1 += __shfl_down_sync(0xffffffffu, n1, o);
        n2 += __shfl_down_sync(0xffffffffu, n2, o);
        d1 += __shfl_down_sync(0xffffffffu, d1, o);
        d2 += __shfl_down_sync(0xffffffffu, d2, o);
    }
    __shared__ float sacc[8];
    float contrib = 0.f;
    if (lane == 0 && node < NN) {
        float np  = fmaxf(sqrtf(pp), 1e-12f);
        float nn1 = fmaxf(sqrtf(n1), 1e-12f);
        float nn2 = fmaxf(sqrtf(n2), 1e-12f);
        contrib = d1 / (np * nn1) + d2 / (np * nn2);
    }
    int wid = threadIdx.x >> 5;
    if (lane == 0) sacc[wid] = contrib;
    __syncthreads();
    if (threadIdx.x == 0) {
        float s = 0.f;
#pragma unroll
        for (int i = 0; i < 8; ++i) s += sacc[i];
        atomicAdd(acc, s);
    }
}

// ---------------- finalize: softmax(beta), loss --------------------------------
__global__ void finalize_kernel(float* __restrict__ out_loss, int write_loss)
{
    float invN = 1.f / (float)NN;
    float b0 = g_beta_raw[0] * invN;
    float b1 = g_beta_raw[1] * invN;
    float b2 = g_beta_raw[2] * invN;
    float m = fmaxf(b0, fmaxf(b1, b2));
    float e0 = expf(b0 - m), e1 = expf(b1 - m), e2 = expf(b2 - m);
    float s = e0 + e1 + e2;
    g_beta[0] = e0 / s;
    g_beta[1] = e1 / s;
    g_beta[2] = e2 / s;
    if (write_loss) *out_loss = 2.0f - g_loss_acc * invN;
}

// ---------------- z_out = b0*z1 + b1*z2 + b2*z0 ---------------------------------
__global__ __launch_bounds__(256)
void zout_kernel(float4* __restrict__ out, const float4* __restrict__ z1,
                 const float4* __restrict__ z2, const float4* __restrict__ z0)
{
    int i = blockIdx.x * blockDim.x + threadIdx.x;
    if (i >= NN * 64) return;
    float b0 = g_beta[0], b1 = g_beta[1], b2 = g_beta[2];
    float4 a = z1[i], b = z2[i], c = z0[i];
    float4 r;
    r.x = b0 * a.x + b1 * b.x + b2 * c.x;
    r.y = b0 * a.y + b1 * b.y + b2 * c.y;
    r.z = b0 * a.z + b1 * b.z + b2 * c.z;
    r.w = b0 * a.w + b1 * b.w + b2 * c.w;
    out[i] = r;
}

// ---------------- host ----------------------------------------------------------
extern "C" void kernel_launch(void* const* d_in, const int* in_sizes, int n_in,
                              void* d_out, int out_size)
{
    const float* feats   = (const float*)d_in[0];
    const int*   src     = (const int*)  d_in[1];
    const int*   dst     = (const int*)  d_in[2];
    const float* vals    = (const float*)d_in[3];
    const float* W_trans = (const float*)d_in[4];
    const float* b_trans = (const float*)d_in[5];
    const float* W_gcn   = (const float*)d_in[6];
    const float* b_gcn   = (const float*)d_in[7];
    const float* a_gcn   = (const float*)d_in[8];
    const float* W1      = (const float*)d_in[9];
    const float* b1      = (const float*)d_in[10];
    const float* bn_g    = (const float*)d_in[11];
    const float* bn_b    = (const float*)d_in[12];
    const float* a_pred  = (const float*)d_in[13];
    const float* W2      = (const float*)d_in[14];
    const float* b2      = (const float*)d_in[15];
    const float* W_att   = (const float*)d_in[16];
    const float* b_att   = (const float*)d_in[17];
    const float* att     = (const float*)d_in[18];

    float *h, *ft, *z0, *z1, *z2, *x, *vp, *stats, *beta_raw, *loss_acc;
    cudaGetSymbolAddress((void**)&h,  g_h);
    cudaGetSymbolAddress((void**)&ft, g_ft);
    cudaGetSymbolAddress((void**)&z0, g_z0);
    cudaGetSymbolAddress((void**)&z1, g_z1);
    cudaGetSymbolAddress((void**)&z2, g_z2);
    cudaGetSymbolAddress((void**)&x,  g_x);
    cudaGetSymbolAddress((void**)&vp, g_vp);
    cudaGetSymbolAddress((void**)&stats,    g_stats);
    cudaGetSymbolAddress((void**)&beta_raw, g_beta_raw);
    cudaGetSymbolAddress((void**)&loss_acc, g_loss_acc);

    const size_t zbytes = (size_t)NN * HH * sizeof(float);
    cudaMemsetAsync(z0, 0, zbytes);
    cudaMemsetAsync(z1, 0, zbytes);
    cudaMemsetAsync(z2, 0, zbytes);
    cudaMemsetAsync(stats, 0, 2 * PHH * sizeof(float));
    cudaMemsetAsync(beta_raw, 0, 3 * sizeof(float));
    cudaMemsetAsync(loss_acc, 0, sizeof(float));

    const int mb = (NN + TBM - 1) / TBM;   // 391

    // h = elu(feats @ W_trans^T + b_trans)   -- 3xTF32
    gemm_tf32_kernel<1, 1><<<dim3(HH / TBN, mb), 256>>>(feats, W_trans, b_trans, h,
                                                        NN, HH, FEATD);

    // all 3 GCN GEMMs fused: ft[N, 768] = h @ [W_gcn0;W_gcn1;W_gcn2]^T -- 3xTF32
    gemm_tf32_kernel<0, 1><<<dim3(3 * HH / TBN, mb), 256>>>(h, W_gcn, nullptr, ft,
                                                            NN, 3 * HH, HH);

    // three SpMM + bias/prelu passes
    float* zs[3] = {z0, z1, z2};
    for (int v = 0; v < PP; ++v) {
        spmm_kernel<<<(EE * 64) / 256, 256>>>((const float4*)ft + v * (HH / 4), 3 * HH / 4,
                                              src + (size_t)v * EE, dst + (size_t)v * EE,
                                              vals + (size_t)v * EE, (float4*)zs[v]);
        bias_prelu_kernel<<<(NN * 64) / 256, 256>>>((float4*)zs[v], b_gcn + (size_t)v * HH,
                                                    a_gcn + v);
    }

    // student predictor -- single-pass tf32 (feeds scalar loss only)
    gemm_tf32_kernel<2, 0><<<dim3(PHH / TBN, mb), 256>>>(z0, W1, b1, x, NN, PHH, HH);
    colstats_kernel<<<dim3(2, 512), 256>>>(x, stats);
    bn_prelu_kernel<<<(NN * PHH / 4) / 256, 256>>>((float4*)x, stats, bn_g, bn_b, a_pred);
    gemm_tf32_kernel<2, 0><<<dim3(HH / TBN, mb), 256>>>(x, W2, b2, vp, NN, HH, PHH);

    // cosine losses vs teachers (views 1 and 2)
    loss_kernel<<<(NN * 32) / 256, 256>>>((const float4*)vp, (const float4*)z1,
                                          (const float4*)z2, loss_acc);

    // type-level attention: z_sum order = [teacher1, teacher2, student]
    gemm_att_tf32_kernel<<<dim3(HH / TBN, mb), 256>>>(z1, W_att, b_att, att, beta_raw + 0, NN, HH);
    gemm_att_tf32_kernel<<<dim3(HH / TBN, mb), 256>>>(z2, W_att, b_att, att, beta_raw + 1, NN, HH);
    gemm_att_tf32_kernel<<<dim3(HH / TBN, mb), 256>>>(z0, W_att, b_att, att, beta_raw + 2, NN, HH);

    float* outf = (float*)d_out;
    int write_loss = (out_size > NN * HH) ? 1 : 0;
    finalize_kernel<<<1, 1>>>(outf + (size_t)NN * HH, write_loss);
    zout_kernel<<<(NN * 64) / 256, 256>>>((float4*)outf, (const float4*)z1,
                                          (const float4*)z2, (const float4*)z0);
}

// round 5
// speedup vs baseline: 1.9035x; 1.1174x over previous
#include <cuda_runtime.h>
#include <math.h>
#include <stdint.h>

// ---------------- problem constants ----------------
#define NN   50000
#define PP   3
#define EE   800000
#define FEATD 1000
#define HH   256
#define PHH  512
#define BN_EPS 1e-5f

// ---------------- device scratch (no allocations allowed) ----------------
__device__ float g_h [(size_t)NN * HH];
__device__ float g_ft[(size_t)NN * (3 * HH)];
__device__ float g_z0[(size_t)NN * HH];
__device__ float g_z1[(size_t)NN * HH];
__device__ float g_z2[(size_t)NN * HH];
__device__ float g_x [(size_t)NN * PHH];
__device__ float g_vp[(size_t)NN * HH];
__device__ float g_stats[2 * PHH];
__device__ float g_beta_raw[3];
__device__ float g_beta[3];
__device__ float g_loss_acc;

// ---------------- tf32 helpers ---------------------------------------------------
__device__ __forceinline__ void mma_tf32(float* c, const uint32_t* a, const uint32_t* b)
{
    asm volatile(
        "mma.sync.aligned.m16n8k8.row.col.f32.tf32.tf32.f32 "
        "{%0,%1,%2,%3}, {%4,%5,%6,%7}, {%8,%9}, {%0,%1,%2,%3};\n"
        : "+f"(c[0]), "+f"(c[1]), "+f"(c[2]), "+f"(c[3])
        : "r"(a[0]), "r"(a[1]), "r"(a[2]), "r"(a[3]), "r"(b[0]), "r"(b[1]));
}

__device__ __forceinline__ uint32_t f2tf32(float x)
{
    uint32_t r;
    asm("cvt.rna.tf32.f32 %0, %1;" : "=r"(r) : "f"(x));
    return r;
}

__device__ __forceinline__ void cp16(uint32_t saddr, const void* gmem, bool pred)
{
    int sz = pred ? 16 : 0;
    asm volatile("cp.async.cg.shared.global [%0], [%1], 16, %2;\n"
                 :: "r"(saddr), "l"(gmem), "r"(sz));
}

// ---------------- tf32 GEMM (2-stage cp.async, 64x32 warp tile) -----------------
// Block tile 128x64, BK=16, 4 warps (2m x 2n), warp tile 64x32 (4x4 m16n8k8).
// SPLITV=1 -> 3xTF32 via bit-mask split (no cvt in hot loop), fp32-grade accuracy.
#define TBM 128
#define TBN 64
#define BKP 16
#define TSTR 20   // padded smem stride (floats) -> conflict-free fragment LDS

#define GEMM_DECL()                                                                 \
    __shared__ float As[2][TBM][TSTR];                                              \
    __shared__ float Ws[2][TBN][TSTR];                                              \
    const int tid  = threadIdx.x;                                                   \
    const int wid  = tid >> 5;                                                      \
    const int lane = tid & 31;                                                      \
    const int g    = lane >> 2;                                                     \
    const int t    = lane & 3;                                                      \
    const int wm   = (wid & 1) << 6;                                                \
    const int wn   = (wid >> 1) << 5;                                               \
    const int bm   = blockIdx.y * TBM;                                              \
    const int bn   = blockIdx.x * TBN;                                              \
    const int ar   = tid >> 2;                                                      \
    const int ac   = (tid & 3) << 2;                                                \
    float acc[4][4][4] = {};

#define GEMM_LOAD_STAGE(S, KO)                                                      \
    {                                                                               \
        int cc = (KO) + ac;                                                         \
        bool pv = (cc < K);                                                         \
        _Pragma("unroll")                                                           \
        for (int q = 0; q < 4; ++q) {                                               \
            int r = ar + (q << 5);                                                  \
            cp16((uint32_t)__cvta_generic_to_shared(&As[S][r][ac]),                 \
                 A + (size_t)(bm + r) * K + cc, pv && (bm + r < M));                \
        }                                                                           \
        _Pragma("unroll")                                                           \
        for (int q = 0; q < 2; ++q) {                                               \
            int r = ar + (q << 5);                                                  \
            cp16((uint32_t)__cvta_generic_to_shared(&Ws[S][r][ac]),                 \
                 W + (size_t)(bn + r) * K + cc, pv);                                \
        }                                                                           \
    }

#define GEMM_TF32_MAINLOOP(SPLITV)                                                  \
    GEMM_DECL();                                                                    \
    GEMM_LOAD_STAGE(0, 0);                                                          \
    asm volatile("cp.async.commit_group;\n" ::: "memory");                          \
    int buf = 0;                                                                    \
    for (int k0 = 0; k0 < K; k0 += BKP) {                                           \
        if (k0 + BKP < K) GEMM_LOAD_STAGE(buf ^ 1, k0 + BKP);                       \
        asm volatile("cp.async.commit_group;\n" ::: "memory");                      \
        asm volatile("cp.async.wait_group 1;\n" ::: "memory");                      \
        __syncthreads();                                                            \
        _Pragma("unroll")                                                           \
        for (int ks = 0; ks < 2; ++ks) {                                            \
            int kk = ks << 3;                                                       \
            uint32_t ab[4][4], bb[4][2];                                            \
            uint32_t asml[4][4], bsml[4][2];                                        \
            _Pragma("unroll")                                                       \
            for (int i = 0; i < 4; ++i) {                                           \
                int rb = wm + (i << 4);                                             \
                float r0 = As[buf][rb + g    ][kk + t    ];                         \
                float r1 = As[buf][rb + g + 8][kk + t    ];                         \
                float r2 = As[buf][rb + g    ][kk + t + 4];                         \
                float r3 = As[buf][rb + g + 8][kk + t + 4];                         \
                if (SPLITV) {                                                       \
                    ab[i][0] = __float_as_uint(r0) & 0xFFFFE000u;                   \
                    ab[i][1] = __float_as_uint(r1) & 0xFFFFE000u;                   \
                    ab[i][2] = __float_as_uint(r2) & 0xFFFFE000u;                   \
                    ab[i][3] = __float_as_uint(r3) & 0xFFFFE000u;                   \
                    asml[i][0] = __float_as_uint(r0 - __uint_as_float(ab[i][0]));   \
                    asml[i][1] = __float_as_uint(r1 - __uint_as_float(ab[i][1]));   \
                    asml[i][2] = __float_as_uint(r2 - __uint_as_float(ab[i][2]));   \
                    asml[i][3] = __float_as_uint(r3 - __uint_as_float(ab[i][3]));   \
                } else {                                                            \
                    ab[i][0] = f2tf32(r0); ab[i][1] = f2tf32(r1);                   \
                    ab[i][2] = f2tf32(r2); ab[i][3] = f2tf32(r3);                   \
                }                                                                   \
            }                                                                       \
            _Pragma("unroll")                                                       \
            for (int j = 0; j < 4; ++j) {                                           \
                int nb = wn + (j << 3);                                             \
                float r0 = Ws[buf][nb + g][kk + t    ];                             \
                float r1 = Ws[buf][nb + g][kk + t + 4];                             \
                if (SPLITV) {                                                       \
                    bb[j][0] = __float_as_uint(r0) & 0xFFFFE000u;                   \
                    bb[j][1] = __float_as_uint(r1) & 0xFFFFE000u;                   \
                    bsml[j][0] = __float_as_uint(r0 - __uint_as_float(bb[j][0]));   \
                    bsml[j][1] = __float_as_uint(r1 - __uint_as_float(bb[j][1]));   \
                } else {                                                            \
                    bb[j][0] = f2tf32(r0); bb[j][1] = f2tf32(r1);                   \
                }                                                                   \
            }                                                                       \
            if (SPLITV) {                                                           \
                _Pragma("unroll")                                                   \
                for (int i = 0; i < 4; ++i)                                         \
                    _Pragma("unroll")                                               \
                    for (int j = 0; j < 4; ++j) {                                   \
                        mma_tf32(acc[i][j], asml[i], bb[j]);                        \
                        mma_tf32(acc[i][j], ab[i], bsml[j]);                        \
                        mma_tf32(acc[i][j], ab[i], bb[j]);                          \
                    }                                                               \
            } else {                                                                \
                _Pragma("unroll")                                                   \
                for (int i = 0; i < 4; ++i)                                         \
                    _Pragma("unroll")                                               \
                    for (int j = 0; j < 4; ++j)                                     \
                        mma_tf32(acc[i][j], ab[i], bb[j]);                          \
            }                                                                       \
        }                                                                           \
        __syncthreads();                                                            \
        buf ^= 1;                                                                   \
    }

// EPI: 0 = raw, 1 = bias+ELU, 2 = bias
template<int EPI, int SPLITV>
__global__ __launch_bounds__(128, 3)
void gemm_tf32_kernel(const float* __restrict__ A, const float* __restrict__ W,
                      const float* __restrict__ bias, float* __restrict__ C,
                      int M, int Nc, int K)
{
    GEMM_TF32_MAINLOOP(SPLITV);

#pragma unroll
    for (int i = 0; i < 4; ++i) {
#pragma unroll
        for (int j = 0; j < 4; ++j) {
            int r0 = bm + wm + (i << 4) + g;
            int r1 = r0 + 8;
            int c0 = bn + wn + (j << 3) + (t << 1);
            float bx = 0.f, by = 0.f;
            if (EPI >= 1) { bx = bias[c0]; by = bias[c0 + 1]; }
            float v0 = acc[i][j][0], v1 = acc[i][j][1];
            float v2 = acc[i][j][2], v3 = acc[i][j][3];
            if (EPI >= 1) { v0 += bx; v1 += by; v2 += bx; v3 += by; }
            if (EPI == 1) {
                v0 = v0 > 0.f ? v0 : expm1f(v0);
                v1 = v1 > 0.f ? v1 : expm1f(v1);
                v2 = v2 > 0.f ? v2 : expm1f(v2);
                v3 = v3 > 0.f ? v3 : expm1f(v3);
            }
            if (r0 < M) *(float2*)(C + (size_t)r0 * Nc + c0) = make_float2(v0, v1);
            if (r1 < M) *(float2*)(C + (size_t)r1 * Nc + c0) = make_float2(v2, v3);
        }
    }
}

// fused attention GEMM: beta += sum over tile of tanh(z@W^T + b) * att
__global__ __launch_bounds__(128, 3)
void gemm_att_tf32_kernel(const float* __restrict__ A, const float* __restrict__ W,
                          const float* __restrict__ bias, const float* __restrict__ att,
                          float* __restrict__ beta_out, int M, int K)
{
    GEMM_TF32_MAINLOOP(0);

    float s = 0.f;
#pragma unroll
    for (int i = 0; i < 4; ++i) {
#pragma unroll
        for (int j = 0; j < 4; ++j) {
            int r0 = bm + wm + (i << 4) + g;
            int r1 = r0 + 8;
            int c0 = bn + wn + (j << 3) + (t << 1);
            float bx = bias[c0], by = bias[c0 + 1];
            float ax = att[c0],  ay = att[c0 + 1];
            if (r0 < M) s += tanhf(acc[i][j][0] + bx) * ax + tanhf(acc[i][j][1] + by) * ay;
            if (r1 < M) s += tanhf(acc[i][j][2] + bx) * ax + tanhf(acc[i][j][3] + by) * ay;
        }
    }
    __shared__ float red[128];
    red[tid] = s;
    __syncthreads();
    for (int o = 64; o > 0; o >>= 1) {
        if (tid < o) red[tid] += red[tid + o];
        __syncthreads();
    }
    if (tid == 0) atomicAdd(beta_out, red[0]);
}

// ---------------- SpMM scatter: z[dst] += val * ft[src]  (vector RED) ----------
__global__ __launch_bounds__(256)
void spmm_kernel(const float4* __restrict__ ft, int stride4,
                 const int* __restrict__ src, const int* __restrict__ dst,
                 const float* __restrict__ vals, float4* __restrict__ z)
{
    int gid = blockIdx.x * blockDim.x + threadIdx.x;
    if (gid >= EE * 64) return;
    int e = gid >> 6;
    int c = gid & 63;
    int s = src[e];
    int d = dst[e];
    float v = vals[e];
    float4 f = ft[(size_t)s * stride4 + c];
    float4* p = &z[(size_t)d * 64 + c];
    asm volatile("red.global.add.v4.f32 [%0], {%1,%2,%3,%4};"
                 :: "l"(p), "f"(v * f.x), "f"(v * f.y), "f"(v * f.z), "f"(v * f.w)
                 : "memory");
}

// ---------------- z = prelu(z + b_gcn[view], a_gcn[view]) ----------------------
__global__ __launch_bounds__(256)
void bias_prelu_kernel(float4* __restrict__ z, const float* __restrict__ b,
                       const float* __restrict__ a_ptr)
{
    int i = blockIdx.x * blockDim.x + threadIdx.x;
    if (i >= NN * 64) return;
    float a = *a_ptr;
    float4 bv = *(const float4*)(b + ((i & 63) << 2));
    float4 x = z[i];
    x.x += bv.x; x.y += bv.y; x.z += bv.z; x.w += bv.w;
    x.x = x.x >= 0.f ? x.x : a * x.x;
    x.y = x.y >= 0.f ? x.y : a * x.y;
    x.z = x.z >= 0.f ? x.z : a * x.z;
    x.w = x.w >= 0.f ? x.w : a * x.w;
    z[i] = x;
}

// ---------------- BN column stats -----------------------------------------------
__global__ __launch_bounds__(256)
void colstats_kernel(const float* __restrict__ x, float* __restrict__ stats)
{
    int c = blockIdx.x * 256 + threadIdx.x;
    float s = 0.f, sq = 0.f;
    for (int r = blockIdx.y; r < NN; r += gridDim.y) {
        float v = x[(size_t)r * PHH + c];
        s += v;
        sq += v * v;
    }
    atomicAdd(&stats[c], s);
    atomicAdd(&stats[PHH + c], sq);
}

// ---------------- BN + PReLU in place -------------------------------------------
__global__ __launch_bounds__(256)
void bn_prelu_kernel(float4* __restrict__ x, const float* __restrict__ stats,
                     const float* __restrict__ g, const float* __restrict__ b,
                     const float* __restrict__ a_ptr)
{
    int i = blockIdx.x * blockDim.x + threadIdx.x;
    if (i >= NN * (PHH / 4)) return;
    int c = (i & (PHH / 4 - 1)) << 2;
    float a = *a_ptr;
    float4 sm = *(const float4*)(stats + c);
    float4 sq = *(const float4*)(stats + PHH + c);
    float4 gv = *(const float4*)(g + c);
    float4 bv = *(const float4*)(b + c);
    float4 v = x[i];
    float invN = 1.f / (float)NN;

    float mu, var, sc, sh, y;
    mu = sm.x * invN; var = sq.x * invN - mu * mu; sc = gv.x * rsqrtf(var + BN_EPS);
    sh = bv.x - mu * sc; y = v.x * sc + sh; v.x = y >= 0.f ? y : a * y;
    mu = sm.y * invN; var = sq.y * invN - mu * mu; sc = gv.y * rsqrtf(var + BN_EPS);
    sh = bv.y - mu * sc; y = v.y * sc + sh; v.y = y >= 0.f ? y : a * y;
    mu = sm.z * invN; var = sq.z * invN - mu * mu; sc = gv.z * rsqrtf(var + BN_EPS);
    sh = bv.z - mu * sc; y = v.z * sc + sh; v.z = y >= 0.f ? y : a * y;
    mu = sm.w * invN; var = sq.w * invN - mu * mu; sc = gv.w * rsqrtf(var + BN_EPS);
    sh = bv.w - mu * sc; y = v.w * sc + sh; v.w = y >= 0.f ? y : a * y;
    x[i] = v;
}

// ---------------- cosine loss accumulation (one warp per node) ------------------
__global__ __launch_bounds__(256)
void loss_kernel(const float4* __restrict__ p, const float4* __restrict__ t1,
                 const float4* __restrict__ t2, float* __restrict__ acc)
{
    int gid  = blockIdx.x * blockDim.x + threadIdx.x;
    int node = gid >> 5;
    int lane = gid & 31;
    float pp = 0.f, n1 = 0.f, n2 = 0.f, d1 = 0.f, d2 = 0.f;
    if (node < NN) {
        size_t base = (size_t)node * 64;
#pragma unroll
        for (int r = 0; r < 2; ++r) {
            float4 a  = p [base + lane + 32 * r];
            float4 b  = t1[base + lane + 32 * r];
            float4 cc = t2[base + lane + 32 * r];
            pp += a.x * a.x + a.y * a.y + a.z * a.z + a.w * a.w;
            n1 += b.x * b.x + b.y * b.y + b.z * b.z + b.w * b.w;
            n2 += cc.x * cc.x + cc.y * cc.y + cc.z * cc.z + cc.w * cc.w;
            d1 += a.x * b.x + a.y * b.y + a.z * b.z + a.w * b.w;
            d2 += a.x * cc.x + a.y * cc.y + a.z * cc.z + a.w * cc.w;
        }
    }
#pragma unroll
    for (int o = 16; o > 0; o >>= 1) {
        pp += __shfl_down_sync(0xffffffffu, pp, o);
        n1 += __shfl_down_sync(0xffffffffu, n1, o);
        n2 += __shfl_down_sync(0xffffffffu, n2, o);
        d1 += __shfl_down_sync(0xffffffffu, d1, o);
        d2 += __shfl_down_sync(0xffffffffu, d2, o);
    }
    __shared__ float sacc[8];
    float contrib = 0.f;
    if (lane == 0 && node < NN) {
        float np  = fmaxf(sqrtf(pp), 1e-12f);
        float nn1 = fmaxf(sqrtf(n1), 1e-12f);
        float nn2 = fmaxf(sqrtf(n2), 1e-12f);
        contrib = d1 / (np * nn1) + d2 / (np * nn2);
    }
    int wid = threadIdx.x >> 5;
    if (lane == 0) sacc[wid] = contrib;
    __syncthreads();
    if (threadIdx.x == 0) {
        float s = 0.f;
#pragma unroll
        for (int i = 0; i < 8; ++i) s += sacc[i];
        atomicAdd(acc, s);
    }
}

// ---------------- finalize: softmax(beta), loss --------------------------------
__global__ void finalize_kernel(float* __restrict__ out_loss, int write_loss)
{
    float invN = 1.f / (float)NN;
    float b0 = g_beta_raw[0] * invN;
    float b1 = g_beta_raw[1] * invN;
    float b2 = g_beta_raw[2] * invN;
    float m = fmaxf(b0, fmaxf(b1, b2));
    float e0 = expf(b0 - m), e1 = expf(b1 - m), e2 = expf(b2 - m);
    float s = e0 + e1 + e2;
    g_beta[0] = e0 / s;
    g_beta[1] = e1 / s;
    g_beta[2] = e2 / s;
    if (write_loss) *out_loss = 2.0f - g_loss_acc * invN;
}

// ---------------- z_out = b0*z1 + b1*z2 + b2*z0 ---------------------------------
__global__ __launch_bounds__(256)
void zout_kernel(float4* __restrict__ out, const float4* __restrict__ z1,
                 const float4* __restrict__ z2, const float4* __restrict__ z0)
{
    int i = blockIdx.x * blockDim.x + threadIdx.x;
    if (i >= NN * 64) return;
    float b0 = g_beta[0], b1 = g_beta[1], b2 = g_beta[2];
    float4 a = z1[i], b = z2[i], c = z0[i];
    float4 r;
    r.x = b0 * a.x + b1 * b.x + b2 * c.x;
    r.y = b0 * a.y + b1 * b.y + b2 * c.y;
    r.z = b0 * a.z + b1 * b.z + b2 * c.z;
    r.w = b0 * a.w + b1 * b.w + b2 * c.w;
    out[i] = r;
}

// ---------------- host ----------------------------------------------------------
extern "C" void kernel_launch(void* const* d_in, const int* in_sizes, int n_in,
                              void* d_out, int out_size)
{
    const float* feats   = (const float*)d_in[0];
    const int*   src     = (const int*)  d_in[1];
    const int*   dst     = (const int*)  d_in[2];
    const float* vals    = (const float*)d_in[3];
    const float* W_trans = (const float*)d_in[4];
    const float* b_trans = (const float*)d_in[5];
    const float* W_gcn   = (const float*)d_in[6];
    const float* b_gcn   = (const float*)d_in[7];
    const float* a_gcn   = (const float*)d_in[8];
    const float* W1      = (const float*)d_in[9];
    const float* b1      = (const float*)d_in[10];
    const float* bn_g    = (const float*)d_in[11];
    const float* bn_b    = (const float*)d_in[12];
    const float* a_pred  = (const float*)d_in[13];
    const float* W2      = (const float*)d_in[14];
    const float* b2      = (const float*)d_in[15];
    const float* W_att   = (const float*)d_in[16];
    const float* b_att   = (const float*)d_in[17];
    const float* att     = (const float*)d_in[18];

    float *h, *ft, *z0, *z1, *z2, *x, *vp, *stats, *beta_raw, *loss_acc;
    cudaGetSymbolAddress((void**)&h,  g_h);
    cudaGetSymbolAddress((void**)&ft, g_ft);
    cudaGetSymbolAddress((void**)&z0, g_z0);
    cudaGetSymbolAddress((void**)&z1, g_z1);
    cudaGetSymbolAddress((void**)&z2, g_z2);
    cudaGetSymbolAddress((void**)&x,  g_x);
    cudaGetSymbolAddress((void**)&vp, g_vp);
    cudaGetSymbolAddress((void**)&stats,    g_stats);
    cudaGetSymbolAddress((void**)&beta_raw, g_beta_raw);
    cudaGetSymbolAddress((void**)&loss_acc, g_loss_acc);

    const size_t zbytes = (size_t)NN * HH * sizeof(float);
    cudaMemsetAsync(z0, 0, zbytes);
    cudaMemsetAsync(z1, 0, zbytes);
    cudaMemsetAsync(z2, 0, zbytes);
    cudaMemsetAsync(stats, 0, 2 * PHH * sizeof(float));
    cudaMemsetAsync(beta_raw, 0, 3 * sizeof(float));
    cudaMemsetAsync(loss_acc, 0, sizeof(float));

    const int mb = (NN + TBM - 1) / TBM;   // 391

    // h = elu(feats @ W_trans^T + b_trans)   -- 3xTF32
    gemm_tf32_kernel<1, 1><<<dim3(HH / TBN, mb), 128>>>(feats, W_trans, b_trans, h,
                                                        NN, HH, FEATD);

    // all 3 GCN GEMMs fused: ft[N, 768] = h @ [W_gcn0;W_gcn1;W_gcn2]^T -- 3xTF32
    gemm_tf32_kernel<0, 1><<<dim3(3 * HH / TBN, mb), 128>>>(h, W_gcn, nullptr, ft,
                                                            NN, 3 * HH, HH);

    // three SpMM + bias/prelu passes
    float* zs[3] = {z0, z1, z2};
    for (int v = 0; v < PP; ++v) {
        spmm_kernel<<<(EE * 64) / 256, 256>>>((const float4*)ft + v * (HH / 4), 3 * HH / 4,
                                              src + (size_t)v * EE, dst + (size_t)v * EE,
                                              vals + (size_t)v * EE, (float4*)zs[v]);
        bias_prelu_kernel<<<(NN * 64) / 256, 256>>>((float4*)zs[v], b_gcn + (size_t)v * HH,
                                                    a_gcn + v);
    }

    // student predictor -- single-pass tf32 (feeds scalar loss only)
    gemm_tf32_kernel<2, 0><<<dim3(PHH / TBN, mb), 128>>>(z0, W1, b1, x, NN, PHH, HH);
    colstats_kernel<<<dim3(2, 512), 256>>>(x, stats);
    bn_prelu_kernel<<<(NN * PHH / 4) / 256, 256>>>((float4*)x, stats, bn_g, bn_b, a_pred);
    gemm_tf32_kernel<2, 0><<<dim3(HH / TBN, mb), 128>>>(x, W2, b2, vp, NN, HH, PHH);

    // cosine losses vs teachers (views 1 and 2)
    loss_kernel<<<(NN * 32) / 256, 256>>>((const float4*)vp, (const float4*)z1,
                                          (const float4*)z2, loss_acc);

    // type-level attention: z_sum order = [teacher1, teacher2, student]
    gemm_att_tf32_kernel<<<dim3(HH / TBN, mb), 128>>>(z1, W_att, b_att, att, beta_raw + 0, NN, HH);
    gemm_att_tf32_kernel<<<dim3(HH / TBN, mb), 128>>>(z2, W_att, b_att, att, beta_raw + 1, NN, HH);
    gemm_att_tf32_kernel<<<dim3(HH / TBN, mb), 128>>>(z0, W_att, b_att, att, beta_raw + 2, NN, HH);

    float* outf = (float*)d_out;
    int write_loss = (out_size > NN * HH) ? 1 : 0;
    finalize_kernel<<<1, 1>>>(outf + (size_t)NN * HH, write_loss);
    zout_kernel<<<(NN * 64) / 256, 256>>>((float4*)outf, (const float4*)z1,
                                          (const float4*)z2, (const float4*)z0);
}